// round 4
// baseline (speedup 1.0000x reference)
#include <cuda_runtime.h>
#include <cuda_fp16.h>
#include <cstdint>

// Problem constants (fixed by the reference).
#define D_IN_   2048
#define D_SAE_  32768
#define N_      8192
#define K_      64

// Gather tiling: CD dims per chunk. fp16 => chunk footprint 32768*CD*2 bytes.
// CD=512 -> 32MB, comfortably L2-resident (126MB L2).
#define CD      512
#define RN      16

// Scratch (device globals — no allocation allowed in kernel_launch).
__device__ __half g_Wth[(size_t)D_SAE_ * D_IN_];  // transposed W, fp16: (D_SAE, D_IN)
__device__ float  g_vals[N_ * K_];                // deduped values

// ---------------------------------------------------------------------------
// Kernel 1 (fused): transpose+convert W_dec (D_IN, D_SAE) fp32 -> g_Wth
// (D_SAE, D_IN) fp16, AND dedupe values (folded into first 2048 blocks).
//
// Tile: 64 d x 64 s. Read: float4 __ldcs (stream fp32 W, read-once, don't
// pollute L2). Write: uint4 of 8 halves -> 128B/warp-quarter contiguous.
// smem tile[s][d] padded to 68 so 16B LDS stays aligned.
// ---------------------------------------------------------------------------
__global__ __launch_bounds__(256)
void transpose_dedupe_kernel(const float* __restrict__ W,
                             const int*   __restrict__ idx,
                             const float* __restrict__ vals) {
    __shared__ float tile[64][68];   // [s_local][d_local]

    int t  = threadIdx.x;            // 0..255
    int s0 = blockIdx.x * 64;
    int d0 = blockIdx.y * 64;

    // ---- read phase: 64 d-rows x 16 float4 = 1024 float4, 4 iters ----
    #pragma unroll
    for (int i = 0; i < 4; ++i) {
        int e  = i * 256 + t;
        int dl = e >> 4;             // d_local 0..63
        int s4 = (e & 15) * 4;       // s_local (float4 granularity)
        float4 v = __ldcs(reinterpret_cast<const float4*>(
            W + (size_t)(d0 + dl) * D_SAE_ + s0 + s4));
        tile[s4 + 0][dl] = v.x;
        tile[s4 + 1][dl] = v.y;
        tile[s4 + 2][dl] = v.z;
        tile[s4 + 3][dl] = v.w;
    }
    __syncthreads();

    // ---- write phase: 64 s-rows x 8 uint4 (8 halves) = 512 tasks, 2 iters --
    #pragma unroll
    for (int i = 0; i < 2; ++i) {
        int task = i * 256 + t;
        int sl = task >> 3;          // s_local 0..63
        int dc = (task & 7) * 8;     // d_local base (8 dims)
        float4 f0 = *reinterpret_cast<const float4*>(&tile[sl][dc]);
        float4 f1 = *reinterpret_cast<const float4*>(&tile[sl][dc + 4]);
        __half2 h0 = __floats2half2_rn(f0.x, f0.y);
        __half2 h1 = __floats2half2_rn(f0.z, f0.w);
        __half2 h2 = __floats2half2_rn(f1.x, f1.y);
        __half2 h3 = __floats2half2_rn(f1.z, f1.w);
        uint4 o;
        o.x = *reinterpret_cast<uint32_t*>(&h0);
        o.y = *reinterpret_cast<uint32_t*>(&h1);
        o.z = *reinterpret_cast<uint32_t*>(&h2);
        o.w = *reinterpret_cast<uint32_t*>(&h3);
        *reinterpret_cast<uint4*>(
            &g_Wth[(size_t)(s0 + sl) * D_IN_ + d0 + dc]) = o;
    }

    // ---- dedupe (first 2048 blocks; 4 rows each). Reference scatter is
    // .set(): LAST duplicate wins -> zero values whose index reappears later.
    int bid = blockIdx.y * gridDim.x + blockIdx.x;
    if (bid < N_ / 4) {
        __shared__ int sidx[4][K_];
        int lr  = t >> 6;            // local row 0..3
        int k   = t & 63;
        int row = bid * 4 + lr;
        int sv  = idx[row * K_ + k];
        sidx[lr][k] = sv;
        __syncthreads();
        bool keep = true;
        #pragma unroll 1
        for (int k2 = k + 1; k2 < K_; ++k2)
            if (sidx[lr][k2] == sv) keep = false;
        g_vals[row * K_ + k] = keep ? vals[row * K_ + k] : 0.0f;
    }
}

// ---------------------------------------------------------------------------
// Kernel 2: the gather-FMA (fp16 W, fp32 accumulate).
//   grid = (N/RN row-tiles, D_IN/CD chunks), chunk is the SLOW grid axis so
//   concurrent CTAs share one 32MB L2-resident feature-slice table.
//   Block = 256 = 64 dim-threads (8 dims, one LDG.128) x 4 row-groups (4 rows).
//   Bias is applied in the epilogue (not held in regs) so the k-loop fits in
//   <=42 regs -> 6 CTAs/SM (75% occupancy ceiling).
// ---------------------------------------------------------------------------
__global__ __launch_bounds__(256, 6)
void gather_kernel(const int* __restrict__ idx,
                   const float* __restrict__ b_dec,
                   float* __restrict__ out) {
    __shared__ int   soff[RN][K_];     // idx * D_IN (element offset into g_Wth)
    __shared__ float sval[RN][K_];

    int r0  = blockIdx.x * RN;
    int d0  = blockIdx.y * CD;
    int tid = threadIdx.x;

    #pragma unroll
    for (int i = tid; i < RN * K_; i += 256) {
        soff[0][i] = idx[r0 * K_ + i] * D_IN_;
        sval[0][i] = g_vals[r0 * K_ + i];
    }
    __syncthreads();

    int td = tid & 63;            // dim-thread
    int tr = tid >> 6;            // row group 0..3
    int d  = d0 + td * 8;         // 8 contiguous dims (16B fp16) per thread

    const __half* Wt = g_Wth;

    #pragma unroll 1
    for (int i = 0; i < 4; ++i) {
        int r = tr * 4 + i;
        float acc[8];
        #pragma unroll
        for (int j = 0; j < 8; ++j) acc[j] = 0.0f;

        #pragma unroll 8
        for (int k = 0; k < K_; ++k) {
            int   off = soff[r][k] + d;
            float v   = sval[r][k];
            uint4 w   = *reinterpret_cast<const uint4*>(Wt + off);
            __half2 h0 = *reinterpret_cast<__half2*>(&w.x);
            __half2 h1 = *reinterpret_cast<__half2*>(&w.y);
            __half2 h2 = *reinterpret_cast<__half2*>(&w.z);
            __half2 h3 = *reinterpret_cast<__half2*>(&w.w);
            float2 f0 = __half22float2(h0);
            float2 f1 = __half22float2(h1);
            float2 f2 = __half22float2(h2);
            float2 f3 = __half22float2(h3);
            acc[0] = fmaf(v, f0.x, acc[0]);
            acc[1] = fmaf(v, f0.y, acc[1]);
            acc[2] = fmaf(v, f1.x, acc[2]);
            acc[3] = fmaf(v, f1.y, acc[3]);
            acc[4] = fmaf(v, f2.x, acc[4]);
            acc[5] = fmaf(v, f2.y, acc[5]);
            acc[6] = fmaf(v, f3.x, acc[6]);
            acc[7] = fmaf(v, f3.y, acc[7]);
        }

        // Epilogue: bias (L1-hot reload, frees 8 regs in the loop) + store.
        float4 b0 = *reinterpret_cast<const float4*>(b_dec + d);
        float4 b1 = *reinterpret_cast<const float4*>(b_dec + d + 4);
        float* orow = out + (size_t)(r0 + r) * D_IN_ + d;
        __stcs(reinterpret_cast<float4*>(orow),
               make_float4(acc[0] + b0.x, acc[1] + b0.y,
                           acc[2] + b0.z, acc[3] + b0.w));
        __stcs(reinterpret_cast<float4*>(orow + 4),
               make_float4(acc[4] + b1.x, acc[5] + b1.y,
                           acc[6] + b1.z, acc[7] + b1.w));
    }
}

// ---------------------------------------------------------------------------
// Launch. Inputs (metadata order): indices(int32 N*K), values(f32 N*K),
// W_dec(f32 D_IN*D_SAE), b_dec(f32 D_IN). Output: f32 N*D_IN.
// Graph-capturable: 2 plain kernel launches, zero allocation, zero sync.
// ---------------------------------------------------------------------------
extern "C" void kernel_launch(void* const* d_in, const int* in_sizes, int n_in,
                              void* d_out, int out_size) {
    const int*   indices = (const int*)  d_in[0];
    const float* values  = (const float*)d_in[1];
    const float* W       = (const float*)d_in[2];
    const float* b       = (const float*)d_in[3];
    float*       out     = (float*)d_out;

    dim3 tg(D_SAE_ / 64, D_IN_ / 64);
    transpose_dedupe_kernel<<<tg, 256>>>(W, indices, values);

    dim3 gg(N_ / RN, D_IN_ / CD);   // x = row tiles (fast), y = d-chunks (slow)
    gather_kernel<<<gg, 256>>>(indices, b, out);
}

// round 5
// speedup vs baseline: 1.2864x; 1.2864x over previous
#include <cuda_runtime.h>
#include <cuda_fp16.h>
#include <cstdint>

// Problem constants (fixed by the reference).
#define D_IN_   2048
#define D_SAE_  32768
#define N_      8192
#define K_      64

// Gather tiling: CD dims per chunk. fp16 => chunk footprint 32768*CD*2 bytes.
// CD=512 -> 32MB, comfortably L2-resident (126MB L2).
#define CD      512
#define RN      16

// Scratch (device globals — no allocation allowed in kernel_launch).
__device__ __half g_Wth[(size_t)D_SAE_ * D_IN_];  // transposed W, fp16: (D_SAE, D_IN)
__device__ float  g_vals[N_ * K_];                // deduped values

// ---------------------------------------------------------------------------
// Kernel 1 (fused, reverted to the R3 layout that measured well):
// transpose+convert W_dec (D_IN, D_SAE) fp32 -> g_Wth (D_SAE, D_IN) fp16,
// AND dedupe values (folded into the first 2048 blocks).
// Tile 32 s x 64 d: warp-coalesced 128B reads, __half2-packed 128B writes,
// tile[32][65] is conflict-free on both phases.
// ---------------------------------------------------------------------------
__global__ __launch_bounds__(256)
void transpose_dedupe_kernel(const float* __restrict__ W,
                             const int*   __restrict__ idx,
                             const float* __restrict__ vals) {
    __shared__ float tile[32][65];

    int tx = threadIdx.x & 31;
    int ty = threadIdx.x >> 5;   // 0..7

    // ---- transpose part ----
    int s = blockIdx.x * 32 + tx;
    #pragma unroll
    for (int j = 0; j < 8; ++j) {
        int d = blockIdx.y * 64 + ty * 8 + j;
        tile[tx][ty * 8 + j] = W[(size_t)d * D_SAE_ + s];   // 128B/warp read
    }
    __syncthreads();

    #pragma unroll
    for (int j = 0; j < 4; ++j) {
        int s_local = ty + 8 * j;
        int d_local = tx * 2;
        __half2 h = __floats2half2_rn(tile[s_local][d_local],
                                      tile[s_local][d_local + 1]);
        *reinterpret_cast<__half2*>(
            &g_Wth[(size_t)(blockIdx.x * 32 + s_local) * D_IN_
                   + blockIdx.y * 64 + d_local]) = h;       // 128B/warp write
    }

    // ---- dedupe (first 2048 blocks; 4 rows each). Reference scatter is
    // .set(): LAST duplicate wins -> zero values whose index reappears later.
    int bid = blockIdx.y * gridDim.x + blockIdx.x;
    if (bid < N_ / 4) {
        __shared__ int sidx[4][K_];
        int t   = threadIdx.x;
        int lr  = t >> 6;            // local row 0..3
        int k   = t & 63;
        int row = bid * 4 + lr;
        int sv  = idx[row * K_ + k];
        sidx[lr][k] = sv;
        __syncthreads();
        bool keep = true;
        #pragma unroll 1
        for (int k2 = k + 1; k2 < K_; ++k2)
            if (sidx[lr][k2] == sv) keep = false;
        g_vals[row * K_ + k] = keep ? vals[row * K_ + k] : 0.0f;
    }
}

// ---------------------------------------------------------------------------
// Kernel 2: the gather-FMA. fp16 W, HFMA2 inner loop, fp32 flush every 4 k.
//   grid = (N/RN row-tiles, D_IN/CD chunks), chunk is the SLOW grid axis so
//   concurrent CTAs share one 32MB L2-resident feature-slice table.
//   Block = 256 = 64 dim-threads (8 dims, one LDG.128) x 4 row-groups (4 rows).
//   Staging packs (w-offset, half2(v,v)) into one 64-bit smem word:
//   inner loop = LDS.64 + IADD + LDG.128 + 4 HFMA2 (+ amortized flush).
//   NO min-blocks clamp: R4 proved register squeezing kills per-thread MLP.
// ---------------------------------------------------------------------------
__global__ __launch_bounds__(256)
void gather_kernel(const int* __restrict__ idx,
                   const float* __restrict__ b_dec,
                   float* __restrict__ out) {
    __shared__ unsigned long long spack[RN][K_];  // lo32: off, hi32: half2(v,v)

    int r0  = blockIdx.x * RN;
    int d0  = blockIdx.y * CD;
    int tid = threadIdx.x;

    #pragma unroll
    for (int i = tid; i < RN * K_; i += 256) {
        int   off = idx[r0 * K_ + i] * D_IN_;      // max 67.1M, fits 32-bit
        float v   = g_vals[r0 * K_ + i];
        __half2 vh = __float2half2_rn(v);
        unsigned int vb = *reinterpret_cast<unsigned int*>(&vh);
        spack[0][i] = (unsigned long long)(unsigned int)off
                    | ((unsigned long long)vb << 32);
    }
    __syncthreads();

    int td = tid & 63;            // dim-thread
    int tr = tid >> 6;            // row group 0..3
    int d  = d0 + td * 8;         // 8 contiguous dims (16B fp16) per thread

    float bb[8];
    {
        float4 b0 = *reinterpret_cast<const float4*>(b_dec + d);
        float4 b1 = *reinterpret_cast<const float4*>(b_dec + d + 4);
        bb[0] = b0.x; bb[1] = b0.y; bb[2] = b0.z; bb[3] = b0.w;
        bb[4] = b1.x; bb[5] = b1.y; bb[6] = b1.z; bb[7] = b1.w;
    }

    const __half* Wt = g_Wth;

    #pragma unroll 1
    for (int i = 0; i < 4; ++i) {
        int r = tr * 4 + i;
        const unsigned long long* sp = spack[r];

        float acc[8];
        #pragma unroll
        for (int j = 0; j < 8; ++j) acc[j] = bb[j];

        #pragma unroll 1
        for (int kk = 0; kk < K_; kk += 4) {
            __half2 a0 = __float2half2_rn(0.0f);
            __half2 a1 = a0, a2 = a0, a3 = a0;
            #pragma unroll
            for (int u = 0; u < 4; ++u) {
                unsigned long long p = sp[kk + u];
                int          off = (int)(unsigned int)p;
                unsigned int vb  = (unsigned int)(p >> 32);
                __half2 vv = *reinterpret_cast<__half2*>(&vb);
                uint4 w = *reinterpret_cast<const uint4*>(Wt + off + d);
                a0 = __hfma2(*reinterpret_cast<__half2*>(&w.x), vv, a0);
                a1 = __hfma2(*reinterpret_cast<__half2*>(&w.y), vv, a1);
                a2 = __hfma2(*reinterpret_cast<__half2*>(&w.z), vv, a2);
                a3 = __hfma2(*reinterpret_cast<__half2*>(&w.w), vv, a3);
            }
            // Flush 4-term half partials into fp32 accumulators.
            float2 f0 = __half22float2(a0);
            float2 f1 = __half22float2(a1);
            float2 f2 = __half22float2(a2);
            float2 f3 = __half22float2(a3);
            acc[0] += f0.x; acc[1] += f0.y;
            acc[2] += f1.x; acc[3] += f1.y;
            acc[4] += f2.x; acc[5] += f2.y;
            acc[6] += f3.x; acc[7] += f3.y;
        }

        float* orow = out + (size_t)(r0 + r) * D_IN_ + d;
        // Streaming stores: don't let the 64MB output evict the W chunk in L2.
        __stcs(reinterpret_cast<float4*>(orow),
               make_float4(acc[0], acc[1], acc[2], acc[3]));
        __stcs(reinterpret_cast<float4*>(orow + 4),
               make_float4(acc[4], acc[5], acc[6], acc[7]));
    }
}

// ---------------------------------------------------------------------------
// Launch. Inputs (metadata order): indices(int32 N*K), values(f32 N*K),
// W_dec(f32 D_IN*D_SAE), b_dec(f32 D_IN). Output: f32 N*D_IN.
// Graph-capturable: 2 plain kernel launches, zero allocation, zero sync.
// ---------------------------------------------------------------------------
extern "C" void kernel_launch(void* const* d_in, const int* in_sizes, int n_in,
                              void* d_out, int out_size) {
    const int*   indices = (const int*)  d_in[0];
    const float* values  = (const float*)d_in[1];
    const float* W       = (const float*)d_in[2];
    const float* b       = (const float*)d_in[3];
    float*       out     = (float*)d_out;

    dim3 tg(D_SAE_ / 32, D_IN_ / 64);
    transpose_dedupe_kernel<<<tg, 256>>>(W, indices, values);

    dim3 gg(N_ / RN, D_IN_ / CD);   // x = row tiles (fast), y = d-chunks (slow)
    gather_kernel<<<gg, 256>>>(indices, b, out);
}